// round 6
// baseline (speedup 1.0000x reference)
#include <cuda_runtime.h>
#include <math.h>

// Problem constants (fixed by the dataset)
#define BN   2
#define SN   2048
#define DN   1024
#define HN   16
#define HDN  64
#define NN   (BN * SN)   // 4096 tokens

// ---------------------------------------------------------------------------
// Scratch (no cudaMalloc allowed): device globals, 16 MB each.
// ---------------------------------------------------------------------------
__device__ float g_Q[NN * DN];
__device__ float g_K[NN * DN];
__device__ float g_V[NN * DN];
__device__ float g_ATT[NN * DN];

// Pass-by-value bundle of the three projection weights/biases/outputs so a
// single fused kernel can select by blockIdx.z (no extra device memory).
struct QKVArgs {
    const float* W[3];
    const float* b[3];
    float*       C[3];
};

// ---------------------------------------------------------------------------
// GEMM core: C[N x M] = A[N x K] @ W[M x K]^T + bias[M]
// N = 4096, M = K = 1024. Block tile 128x128, K-tile 16, 256 threads,
// 8x8 register micro-tile per thread.
// Global loads register-prefetched (4 independent LDG.128 per thread per
// tile); shared memory DOUBLE-BUFFERED: ONE __syncthreads per 16-deep K-tile.
// ---------------------------------------------------------------------------
__device__ __forceinline__
void gemm_bias_core(const float* __restrict__ A,
                    const float* __restrict__ W,
                    const float* __restrict__ bias,
                    float* __restrict__ C)
{
    const int Kd = DN;
    const int Md = DN;

    __shared__ float As[2][16][128];   // As[buf][k][row]
    __shared__ float Bs[2][16][128];   // Bs[buf][k][col]

    const int tid  = threadIdx.x;
    const int row0 = blockIdx.y * 128;
    const int col0 = blockIdx.x * 128;
    const int tx   = tid & 15;
    const int ty   = tid >> 4;

    // global-load assignment: two float4 of A and two of W per thread per tile
    const int lrow = tid >> 1;          // 0..127
    const int lkq  = (tid & 1) * 8;     // 0 or 8

    const float4* Ap = (const float4*)(A + (size_t)(row0 + lrow) * Kd + lkq);
    const float4* Wp = (const float4*)(W + (size_t)(col0 + lrow) * Kd + lkq);

    float acc[8][8];
#pragma unroll
    for (int i = 0; i < 8; i++)
#pragma unroll
        for (int j = 0; j < 8; j++) acc[i][j] = 0.0f;

    // prologue: fetch tile 0 into registers, stage into buffer 0
    float4 av0 = Ap[0], av1 = Ap[1];
    float4 wv0 = Wp[0], wv1 = Wp[1];
    As[0][lkq + 0][lrow] = av0.x;  As[0][lkq + 1][lrow] = av0.y;
    As[0][lkq + 2][lrow] = av0.z;  As[0][lkq + 3][lrow] = av0.w;
    As[0][lkq + 4][lrow] = av1.x;  As[0][lkq + 5][lrow] = av1.y;
    As[0][lkq + 6][lrow] = av1.z;  As[0][lkq + 7][lrow] = av1.w;
    Bs[0][lkq + 0][lrow] = wv0.x;  Bs[0][lkq + 1][lrow] = wv0.y;
    Bs[0][lkq + 2][lrow] = wv0.z;  Bs[0][lkq + 3][lrow] = wv0.w;
    Bs[0][lkq + 4][lrow] = wv1.x;  Bs[0][lkq + 5][lrow] = wv1.y;
    Bs[0][lkq + 6][lrow] = wv1.z;  Bs[0][lkq + 7][lrow] = wv1.w;
    __syncthreads();

    const int T = Kd / 16;   // 64 K-tiles
    for (int t = 0; t < T; t++) {
        const int cur = t & 1;
        const int nxt = cur ^ 1;

        // prefetch next tile's globals while computing on this one
        if (t + 1 < T) {
            av0 = Ap[(t + 1) * 4];     av1 = Ap[(t + 1) * 4 + 1];
            wv0 = Wp[(t + 1) * 4];     wv1 = Wp[(t + 1) * 4 + 1];
        }

#pragma unroll
        for (int kk = 0; kk < 16; kk++) {
            float a[8], b[8];
            *(float4*)&a[0] = *(const float4*)&As[cur][kk][ty * 8];
            *(float4*)&a[4] = *(const float4*)&As[cur][kk][ty * 8 + 4];
            *(float4*)&b[0] = *(const float4*)&Bs[cur][kk][tx * 8];
            *(float4*)&b[4] = *(const float4*)&Bs[cur][kk][tx * 8 + 4];
#pragma unroll
            for (int i = 0; i < 8; i++)
#pragma unroll
                for (int j = 0; j < 8; j++)
                    acc[i][j] += a[i] * b[j];
        }

        // stage next tile into the idle buffer; single barrier per iteration
        if (t + 1 < T) {
            As[nxt][lkq + 0][lrow] = av0.x;  As[nxt][lkq + 1][lrow] = av0.y;
            As[nxt][lkq + 2][lrow] = av0.z;  As[nxt][lkq + 3][lrow] = av0.w;
            As[nxt][lkq + 4][lrow] = av1.x;  As[nxt][lkq + 5][lrow] = av1.y;
            As[nxt][lkq + 6][lrow] = av1.z;  As[nxt][lkq + 7][lrow] = av1.w;
            Bs[nxt][lkq + 0][lrow] = wv0.x;  Bs[nxt][lkq + 1][lrow] = wv0.y;
            Bs[nxt][lkq + 2][lrow] = wv0.z;  Bs[nxt][lkq + 3][lrow] = wv0.w;
            Bs[nxt][lkq + 4][lrow] = wv1.x;  Bs[nxt][lkq + 5][lrow] = wv1.y;
            Bs[nxt][lkq + 6][lrow] = wv1.z;  Bs[nxt][lkq + 7][lrow] = wv1.w;
            __syncthreads();
        }
    }

    float bb[8];
#pragma unroll
    for (int j = 0; j < 8; j++) bb[j] = bias[col0 + tx * 8 + j];

#pragma unroll
    for (int i = 0; i < 8; i++) {
        const int r = row0 + ty * 8 + i;
        float* Cp = C + (size_t)r * Md + col0 + tx * 8;
        float4 o0, o1;
        o0.x = acc[i][0] + bb[0];
        o0.y = acc[i][1] + bb[1];
        o0.z = acc[i][2] + bb[2];
        o0.w = acc[i][3] + bb[3];
        o1.x = acc[i][4] + bb[4];
        o1.y = acc[i][5] + bb[5];
        o1.z = acc[i][6] + bb[6];
        o1.w = acc[i][7] + bb[7];
        *(float4*)(Cp)     = o0;
        *(float4*)(Cp + 4) = o1;
    }
}

// Fused QKV: blockIdx.z in {0,1,2} selects the projection. One grid, one
// ragged tail instead of three, and X stays hot in L2 across z-slices.
__global__ __launch_bounds__(256)
void qkv_gemm_kernel(const float* __restrict__ A, QKVArgs args)
{
    const int z = blockIdx.z;
    gemm_bias_core(A, args.W[z], args.b[z], args.C[z]);
}

__global__ __launch_bounds__(256)
void gemm_bias_kernel(const float* __restrict__ A,
                      const float* __restrict__ W,
                      const float* __restrict__ bias,
                      float* __restrict__ C)
{
    gemm_bias_core(A, W, bias, C);
}

// ---------------------------------------------------------------------------
// Flash attention (fp32): causal + key-padding mask, online softmax.
// Tile BQ=64 queries x BK=64 keys, HD=64. 256 threads.
// Thread (tx = tid&15, ty = tid>>4) owns rows {ty+16m} x cols {tx*4+c}: 4x4.
// Smem layout: every LDS is within-one-row or a 16-lane broadcast.
// K is stored transposed (KPs[k][j]); P reuses KPs. 48 KB static smem.
// Tile specialization: interior all-valid tiles (~97% of visits) skip the
// per-element causal/padding predicates entirely.
// ---------------------------------------------------------------------------
__global__ __launch_bounds__(256)
void attn_kernel(const float* __restrict__ Qb,
                 const float* __restrict__ Kb,
                 const float* __restrict__ Vb,
                 const int*   __restrict__ kpm,
                 float* __restrict__ O)
{
    __shared__ float Qs[64 * 64];    // Qs[r][k]
    __shared__ float KPs[64 * 64];   // first K^T: KPs[k][j]; then P: KPs[r][j]
    __shared__ float Vs[64 * 64];    // Vs[k][d]

    const int tid = threadIdx.x;
    const int q0  = blockIdx.x * 64;
    const int bh  = blockIdx.y;
    const int b   = bh >> 4;
    const int h   = bh & 15;
    const int tx  = tid & 15;
    const int ty  = tid >> 4;

    // ---- load Q tile (rows q0..q0+63, head slice) ----
    {
        const int r = tid >> 2, seg = tid & 3;
        const float4* src =
            (const float4*)(Qb + (size_t)(b * SN + q0 + r) * DN + h * HDN + seg * 16);
        float4* dst = (float4*)(Qs + r * 64 + seg * 16);
#pragma unroll
        for (int q = 0; q < 4; q++) dst[q] = src[q];
    }

    float m_i[4], l_i[4], o_acc[4][4];
#pragma unroll
    for (int m = 0; m < 4; m++) {
        m_i[m] = -1e30f;
        l_i[m] = 0.0f;
#pragma unroll
        for (int c = 0; c < 4; c++) o_acc[m][c] = 0.0f;
    }

    const int* kpm_b = kpm + b * SN;

    for (int j0 = 0; j0 <= q0; j0 += 64) {
        __syncthreads();  // previous iteration (and Q load) fully consumed

        // ---- load K (transposed into KPs) and V ----
        {
            const int r = tid >> 2, seg = tid & 3;   // r = key index in tile
            const float4* ks =
                (const float4*)(Kb + (size_t)(b * SN + j0 + r) * DN + h * HDN + seg * 16);
#pragma unroll
            for (int q = 0; q < 4; q++) {
                float4 kv = ks[q];
                const int kk = seg * 16 + q * 4;
                KPs[(kk + 0) * 64 + r] = kv.x;
                KPs[(kk + 1) * 64 + r] = kv.y;
                KPs[(kk + 2) * 64 + r] = kv.z;
                KPs[(kk + 3) * 64 + r] = kv.w;
            }
            const float4* vsrc =
                (const float4*)(Vb + (size_t)(b * SN + j0 + r) * DN + h * HDN + seg * 16);
            float4* vdst = (float4*)(Vs + r * 64 + seg * 16);
#pragma unroll
            for (int q = 0; q < 4; q++) vdst[q] = vsrc[q];
        }

        // per-thread key-padding mask for keys j0+tx*4 .. +3
        const int4 mv = *(const int4*)(kpm_b + j0 + tx * 4);
        const int tvalid = (mv.x == 0) | (mv.y == 0) | (mv.z == 0) | (mv.w == 0);
        const int tall   = (mv.x == 0) & (mv.y == 0) & (mv.z == 0) & (mv.w == 0);
        const int anyv = __syncthreads_or(tvalid);   // also orders K/V smem writes
        const int allv = __syncthreads_and(tall);
        if (!anyv) continue;  // fully padded key tile: contributes nothing
        const bool fast = (j0 + 64 <= q0) && allv;   // no causal/pad mask needed

        // ---- scores s[m][c] = Q[r_m] . K[j_c] ----
        float s[4][4];
#pragma unroll
        for (int m = 0; m < 4; m++)
#pragma unroll
            for (int c = 0; c < 4; c++) s[m][c] = 0.0f;

        for (int kk = 0; kk < 64; kk += 4) {
            float qa[16], ka[16];
#pragma unroll
            for (int m = 0; m < 4; m++)
                *(float4*)&qa[m * 4] = *(const float4*)&Qs[(ty + 16 * m) * 64 + kk];
#pragma unroll
            for (int u = 0; u < 4; u++)
                *(float4*)&ka[u * 4] = *(const float4*)&KPs[(kk + u) * 64 + tx * 4];
#pragma unroll
            for (int u = 0; u < 4; u++)
#pragma unroll
                for (int m = 0; m < 4; m++)
#pragma unroll
                    for (int c = 0; c < 4; c++)
                        s[m][c] += qa[m * 4 + u] * ka[u * 4 + c];
        }

        // ---- mask + online softmax update ----
        if (fast) {
#pragma unroll
            for (int m = 0; m < 4; m++) {
                float mx = -1e30f;
#pragma unroll
                for (int c = 0; c < 4; c++) {
                    float v = s[m][c] * 0.125f;     // 1/sqrt(64)
                    s[m][c] = v;
                    mx = fmaxf(mx, v);
                }
#pragma unroll
                for (int off = 8; off >= 1; off >>= 1)
                    mx = fmaxf(mx, __shfl_xor_sync(0xffffffffu, mx, off));
                const float mnew = fmaxf(m_i[m], mx);
                const float corr = __expf(m_i[m] - mnew);
                m_i[m] = mnew;
                float ps = 0.0f;
#pragma unroll
                for (int c = 0; c < 4; c++) {
                    float p = __expf(s[m][c] - mnew);
                    s[m][c] = p;
                    ps += p;
                }
#pragma unroll
                for (int off = 8; off >= 1; off >>= 1)
                    ps += __shfl_xor_sync(0xffffffffu, ps, off);
                l_i[m] = l_i[m] * corr + ps;
#pragma unroll
                for (int c = 0; c < 4; c++) o_acc[m][c] *= corr;
            }
        } else {
            const int msk[4] = {mv.x, mv.y, mv.z, mv.w};
#pragma unroll
            for (int m = 0; m < 4; m++) {
                const int r = q0 + ty + 16 * m;    // global query row
                const int jb = j0 + tx * 4;
                float mx = -1e30f;
#pragma unroll
                for (int c = 0; c < 4; c++) {
                    float v = s[m][c] * 0.125f;     // 1/sqrt(64)
                    if ((jb + c > r) || (msk[c] != 0)) v = -1e30f;
                    s[m][c] = v;
                    mx = fmaxf(mx, v);
                }
#pragma unroll
                for (int off = 8; off >= 1; off >>= 1)
                    mx = fmaxf(mx, __shfl_xor_sync(0xffffffffu, mx, off));
                const float mnew = fmaxf(m_i[m], mx);
                const float corr = __expf(m_i[m] - mnew);
                m_i[m] = mnew;
                float ps = 0.0f;
#pragma unroll
                for (int c = 0; c < 4; c++) {
                    float p = __expf(s[m][c] - mnew);
                    s[m][c] = p;
                    ps += p;
                }
#pragma unroll
                for (int off = 8; off >= 1; off >>= 1)
                    ps += __shfl_xor_sync(0xffffffffu, ps, off);
                l_i[m] = l_i[m] * corr + ps;
#pragma unroll
                for (int c = 0; c < 4; c++) o_acc[m][c] *= corr;
            }
        }

        __syncthreads();  // everyone done reading KPs as K^T
        // ---- write P into KPs (row-major: P[r][j]) ----
#pragma unroll
        for (int m = 0; m < 4; m++) {
            float4 pv;
            pv.x = s[m][0]; pv.y = s[m][1]; pv.z = s[m][2]; pv.w = s[m][3];
            *(float4*)&KPs[(ty + 16 * m) * 64 + tx * 4] = pv;
        }
        __syncthreads();

        // ---- O += P @ V ----
        for (int kk = 0; kk < 64; kk += 4) {
            float va[16], pa[16];
#pragma unroll
            for (int u = 0; u < 4; u++)
                *(float4*)&va[u * 4] = *(const float4*)&Vs[(kk + u) * 64 + tx * 4];
#pragma unroll
            for (int m = 0; m < 4; m++)
                *(float4*)&pa[m * 4] = *(const float4*)&KPs[(ty + 16 * m) * 64 + kk];
#pragma unroll
            for (int u = 0; u < 4; u++)
#pragma unroll
                for (int m = 0; m < 4; m++)
#pragma unroll
                    for (int c = 0; c < 4; c++)
                        o_acc[m][c] += pa[m * 4 + u] * va[u * 4 + c];
        }
    }

    // ---- normalize + write ----
#pragma unroll
    for (int m = 0; m < 4; m++) {
        const float inv = 1.0f / l_i[m];
        const int r = q0 + ty + 16 * m;
        float4 res;
        res.x = o_acc[m][0] * inv;
        res.y = o_acc[m][1] * inv;
        res.z = o_acc[m][2] * inv;
        res.w = o_acc[m][3] * inv;
        *(float4*)(O + (size_t)(b * SN + r) * DN + h * HDN + tx * 4) = res;
    }
}

// ---------------------------------------------------------------------------
// Launch
// ---------------------------------------------------------------------------
extern "C" void kernel_launch(void* const* d_in, const int* in_sizes, int n_in,
                              void* d_out, int out_size)
{
    const float* X   = (const float*)d_in[0];
    const int*   kpm = (const int*)  d_in[1];
    const float* Wq  = (const float*)d_in[2];
    const float* bq  = (const float*)d_in[3];
    const float* Wk  = (const float*)d_in[4];
    const float* bk  = (const float*)d_in[5];
    const float* Wv  = (const float*)d_in[6];
    const float* bv  = (const float*)d_in[7];
    const float* Wo  = (const float*)d_in[8];
    const float* bo  = (const float*)d_in[9];
    float* out = (float*)d_out;

    float *Qd, *Kd, *Vd, *Ad;
    cudaGetSymbolAddress((void**)&Qd, g_Q);
    cudaGetSymbolAddress((void**)&Kd, g_K);
    cudaGetSymbolAddress((void**)&Vd, g_V);
    cudaGetSymbolAddress((void**)&Ad, g_ATT);

    QKVArgs args;
    args.W[0] = Wq; args.b[0] = bq; args.C[0] = Qd;
    args.W[1] = Wk; args.b[1] = bk; args.C[1] = Kd;
    args.W[2] = Wv; args.b[2] = bv; args.C[2] = Vd;

    dim3 gqkv(DN / 128, NN / 128, 3);   // (8, 32, 3) = 768 CTAs
    dim3 gg(DN / 128, NN / 128);        // (8, 32)
    dim3 bg(256);

    qkv_gemm_kernel<<<gqkv, bg>>>(X, args);

    dim3 ga(SN / 64, BN * HN);          // (32, 32)
    attn_kernel<<<ga, bg>>>(Qd, Kd, Vd, kpm, Ad);

    gemm_bias_kernel<<<gg, bg>>>(Ad, Wo, bo, out);
}

// round 8
// speedup vs baseline: 1.0747x; 1.0747x over previous
#include <cuda_runtime.h>
#include <math.h>

// Problem constants (fixed by the dataset)
#define BN   2
#define SN   2048
#define DN   1024
#define HN   16
#define HDN  64
#define NN   (BN * SN)   // 4096 tokens

// ---------------------------------------------------------------------------
// Scratch (no cudaMalloc allowed): device globals, 16 MB each.
// ---------------------------------------------------------------------------
__device__ float g_Q[NN * DN];
__device__ float g_K[NN * DN];
__device__ float g_V[NN * DN];
__device__ float g_ATT[NN * DN];

// ---------------------------------------------------------------------------
// Packed f32x2 helpers (FFMA2: 2 fp32 FMAs per instruction; ptxas never
// emits this from C++ — PTX-only path, sm_100+).
// ---------------------------------------------------------------------------
__device__ __forceinline__ unsigned long long pk_dup(float x) {
    unsigned long long r;
    asm("mov.b64 %0, {%1, %1};" : "=l"(r) : "f"(x));
    return r;
}
__device__ __forceinline__ void fma2(unsigned long long& acc,
                                     unsigned long long a,
                                     unsigned long long b) {
    asm("fma.rn.f32x2 %0, %1, %2, %0;" : "+l"(acc) : "l"(a), "l"(b));
}
__device__ __forceinline__ void mul2(unsigned long long& d,
                                     unsigned long long a,
                                     unsigned long long b) {
    asm("mul.rn.f32x2 %0, %1, %2;" : "=l"(d) : "l"(a), "l"(b));
}
__device__ __forceinline__ void unpk2(unsigned long long v, float& lo, float& hi) {
    asm("mov.b64 {%0, %1}, %2;" : "=f"(lo), "=f"(hi) : "l"(v));
}

// Pass-by-value bundle of the three projection weights/biases/outputs so a
// single fused kernel can select by blockIdx.z (no extra device memory).
struct QKVArgs {
    const float* W[3];
    const float* b[3];
    float*       C[3];
};

// ---------------------------------------------------------------------------
// GEMM core: C[N x M] = A[N x K] @ W[M x K]^T + bias[M]
// N = 4096, M = K = 1024. Block tile 128x128, K-tile 16, 256 threads,
// 8x8 register micro-tile per thread; accumulators are f32x2 pairs updated
// with fma.rn.f32x2. The B-operand pairs are loaded straight from smem as
// 64-bit words (no re-pack movs); only the A broadcast needs a pack.
// Global loads register-prefetched; smem double-buffered: ONE barrier/tile.
// ---------------------------------------------------------------------------
__device__ __forceinline__
void gemm_bias_core(const float* __restrict__ A,
                    const float* __restrict__ W,
                    const float* __restrict__ bias,
                    float* __restrict__ C)
{
    const int Kd = DN;
    const int Md = DN;

    __shared__ float As[2][16][128];   // As[buf][k][row]
    __shared__ float Bs[2][16][128];   // Bs[buf][k][col]

    const int tid  = threadIdx.x;
    const int row0 = blockIdx.y * 128;
    const int col0 = blockIdx.x * 128;
    const int tx   = tid & 15;
    const int ty   = tid >> 4;

    const int lrow = tid >> 1;          // 0..127
    const int lkq  = (tid & 1) * 8;     // 0 or 8

    const float4* Ap = (const float4*)(A + (size_t)(row0 + lrow) * Kd + lkq);
    const float4* Wp = (const float4*)(W + (size_t)(col0 + lrow) * Kd + lkq);

    unsigned long long acc2[8][4];      // acc2[i][jp] = (c[i][2jp], c[i][2jp+1])
#pragma unroll
    for (int i = 0; i < 8; i++)
#pragma unroll
        for (int jp = 0; jp < 4; jp++) acc2[i][jp] = 0ull;

    // prologue: fetch tile 0 into registers, stage into buffer 0
    float4 av0 = Ap[0], av1 = Ap[1];
    float4 wv0 = Wp[0], wv1 = Wp[1];
    As[0][lkq + 0][lrow] = av0.x;  As[0][lkq + 1][lrow] = av0.y;
    As[0][lkq + 2][lrow] = av0.z;  As[0][lkq + 3][lrow] = av0.w;
    As[0][lkq + 4][lrow] = av1.x;  As[0][lkq + 5][lrow] = av1.y;
    As[0][lkq + 6][lrow] = av1.z;  As[0][lkq + 7][lrow] = av1.w;
    Bs[0][lkq + 0][lrow] = wv0.x;  Bs[0][lkq + 1][lrow] = wv0.y;
    Bs[0][lkq + 2][lrow] = wv0.z;  Bs[0][lkq + 3][lrow] = wv0.w;
    Bs[0][lkq + 4][lrow] = wv1.x;  Bs[0][lkq + 5][lrow] = wv1.y;
    Bs[0][lkq + 6][lrow] = wv1.z;  Bs[0][lkq + 7][lrow] = wv1.w;
    __syncthreads();

    const int T = Kd / 16;   // 64 K-tiles
    for (int t = 0; t < T; t++) {
        const int cur = t & 1;
        const int nxt = cur ^ 1;

        if (t + 1 < T) {
            av0 = Ap[(t + 1) * 4];     av1 = Ap[(t + 1) * 4 + 1];
            wv0 = Wp[(t + 1) * 4];     wv1 = Wp[(t + 1) * 4 + 1];
        }

#pragma unroll
        for (int kk = 0; kk < 16; kk++) {
            float a[8];
            *(float4*)&a[0] = *(const float4*)&As[cur][kk][ty * 8];
            *(float4*)&a[4] = *(const float4*)&As[cur][kk][ty * 8 + 4];
            // B pairs straight from smem as 64-bit words (8B-aligned)
            const unsigned long long* bp =
                (const unsigned long long*)&Bs[cur][kk][tx * 8];
            unsigned long long b2[4];
            b2[0] = bp[0]; b2[1] = bp[1]; b2[2] = bp[2]; b2[3] = bp[3];
#pragma unroll
            for (int i = 0; i < 8; i++) {
                const unsigned long long a2 = pk_dup(a[i]);
#pragma unroll
                for (int jp = 0; jp < 4; jp++)
                    fma2(acc2[i][jp], a2, b2[jp]);
            }
        }

        if (t + 1 < T) {
            As[nxt][lkq + 0][lrow] = av0.x;  As[nxt][lkq + 1][lrow] = av0.y;
            As[nxt][lkq + 2][lrow] = av0.z;  As[nxt][lkq + 3][lrow] = av0.w;
            As[nxt][lkq + 4][lrow] = av1.x;  As[nxt][lkq + 5][lrow] = av1.y;
            As[nxt][lkq + 6][lrow] = av1.z;  As[nxt][lkq + 7][lrow] = av1.w;
            Bs[nxt][lkq + 0][lrow] = wv0.x;  Bs[nxt][lkq + 1][lrow] = wv0.y;
            Bs[nxt][lkq + 2][lrow] = wv0.z;  Bs[nxt][lkq + 3][lrow] = wv0.w;
            Bs[nxt][lkq + 4][lrow] = wv1.x;  Bs[nxt][lkq + 5][lrow] = wv1.y;
            Bs[nxt][lkq + 6][lrow] = wv1.z;  Bs[nxt][lkq + 7][lrow] = wv1.w;
            __syncthreads();
        }
    }

    float bb[8];
#pragma unroll
    for (int j = 0; j < 8; j++) bb[j] = bias[col0 + tx * 8 + j];

#pragma unroll
    for (int i = 0; i < 8; i++) {
        const int r = row0 + ty * 8 + i;
        float* Cp = C + (size_t)r * Md + col0 + tx * 8;
        float c[8];
#pragma unroll
        for (int jp = 0; jp < 4; jp++)
            unpk2(acc2[i][jp], c[2 * jp], c[2 * jp + 1]);
        float4 o0, o1;
        o0.x = c[0] + bb[0];  o0.y = c[1] + bb[1];
        o0.z = c[2] + bb[2];  o0.w = c[3] + bb[3];
        o1.x = c[4] + bb[4];  o1.y = c[5] + bb[5];
        o1.z = c[6] + bb[6];  o1.w = c[7] + bb[7];
        *(float4*)(Cp)     = o0;
        *(float4*)(Cp + 4) = o1;
    }
}

// Fused QKV: blockIdx.z in {0,1,2} selects the projection.
__global__ __launch_bounds__(256, 2)
void qkv_gemm_kernel(const float* __restrict__ A, QKVArgs args)
{
    const int z = blockIdx.z;
    gemm_bias_core(A, args.W[z], args.b[z], args.C[z]);
}

__global__ __launch_bounds__(256, 2)
void gemm_bias_kernel(const float* __restrict__ A,
                      const float* __restrict__ W,
                      const float* __restrict__ bias,
                      float* __restrict__ C)
{
    gemm_bias_core(A, W, bias, C);
}

// ---------------------------------------------------------------------------
// Flash attention (fp32): causal + key-padding mask, online softmax.
// Tile BQ=64 x BK=64, HD=64, 256 threads; thread owns 4x4 of the score tile.
// QK^T and P@V inner products use fma.rn.f32x2; the K/V operand pairs load
// straight from smem as 64-bit words. Softmax/masking stays scalar fp32.
// ---------------------------------------------------------------------------
__global__ __launch_bounds__(256, 2)
void attn_kernel(const float* __restrict__ Qb,
                 const float* __restrict__ Kb,
                 const float* __restrict__ Vb,
                 const int*   __restrict__ kpm,
                 float* __restrict__ O)
{
    __shared__ float Qs[64 * 64];    // Qs[r][k]
    __shared__ float KPs[64 * 64];   // first K^T: KPs[k][j]; then P: KPs[r][j]
    __shared__ float Vs[64 * 64];    // Vs[k][d]

    const int tid = threadIdx.x;
    const int q0  = blockIdx.x * 64;
    const int bh  = blockIdx.y;
    const int b   = bh >> 4;
    const int h   = bh & 15;
    const int tx  = tid & 15;
    const int ty  = tid >> 4;

    // ---- load Q tile ----
    {
        const int r = tid >> 2, seg = tid & 3;
        const float4* src =
            (const float4*)(Qb + (size_t)(b * SN + q0 + r) * DN + h * HDN + seg * 16);
        float4* dst = (float4*)(Qs + r * 64 + seg * 16);
#pragma unroll
        for (int q = 0; q < 4; q++) dst[q] = src[q];
    }

    float m_i[4], l_i[4];
    unsigned long long o2[4][2];     // packed O accumulators: pairs over c
#pragma unroll
    for (int m = 0; m < 4; m++) {
        m_i[m] = -1e30f;
        l_i[m] = 0.0f;
        o2[m][0] = 0ull;
        o2[m][1] = 0ull;
    }

    const int* kpm_b = kpm + b * SN;

    for (int j0 = 0; j0 <= q0; j0 += 64) {
        __syncthreads();  // previous iteration (and Q load) fully consumed

        // ---- load K (transposed into KPs) and V ----
        {
            const int r = tid >> 2, seg = tid & 3;   // r = key index in tile
            const float4* ks =
                (const float4*)(Kb + (size_t)(b * SN + j0 + r) * DN + h * HDN + seg * 16);
#pragma unroll
            for (int q = 0; q < 4; q++) {
                float4 kv = ks[q];
                const int kk = seg * 16 + q * 4;
                KPs[(kk + 0) * 64 + r] = kv.x;
                KPs[(kk + 1) * 64 + r] = kv.y;
                KPs[(kk + 2) * 64 + r] = kv.z;
                KPs[(kk + 3) * 64 + r] = kv.w;
            }
            const float4* vsrc =
                (const float4*)(Vb + (size_t)(b * SN + j0 + r) * DN + h * HDN + seg * 16);
            float4* vdst = (float4*)(Vs + r * 64 + seg * 16);
#pragma unroll
            for (int q = 0; q < 4; q++) vdst[q] = vsrc[q];
        }

        // per-thread key-padding mask for keys j0+tx*4 .. +3
        const int4 mv = *(const int4*)(kpm_b + j0 + tx * 4);
        const int tvalid = (mv.x == 0) | (mv.y == 0) | (mv.z == 0) | (mv.w == 0);
        const int tall   = (mv.x == 0) & (mv.y == 0) & (mv.z == 0) & (mv.w == 0);
        const int anyv = __syncthreads_or(tvalid);   // also orders K/V smem writes
        const int allv = __syncthreads_and(tall);
        if (!anyv) continue;  // fully padded key tile
        const bool fast = (j0 + 64 <= q0) && allv;   // no causal/pad mask needed

        // ---- scores: s2[m][p] = packed pair (s[m][2p], s[m][2p+1]) ----
        unsigned long long s2[4][2];
#pragma unroll
        for (int m = 0; m < 4; m++) { s2[m][0] = 0ull; s2[m][1] = 0ull; }

        for (int kk = 0; kk < 64; kk += 4) {
            float qa[16];
#pragma unroll
            for (int m = 0; m < 4; m++)
                *(float4*)&qa[m * 4] = *(const float4*)&Qs[(ty + 16 * m) * 64 + kk];
#pragma unroll
            for (int u = 0; u < 4; u++) {
                const unsigned long long* kp =
                    (const unsigned long long*)&KPs[(kk + u) * 64 + tx * 4];
                const unsigned long long k20 = kp[0];
                const unsigned long long k21 = kp[1];
#pragma unroll
                for (int m = 0; m < 4; m++) {
                    const unsigned long long q2 = pk_dup(qa[m * 4 + u]);
                    fma2(s2[m][0], q2, k20);
                    fma2(s2[m][1], q2, k21);
                }
            }
        }

        float s[4][4];
#pragma unroll
        for (int m = 0; m < 4; m++) {
            unpk2(s2[m][0], s[m][0], s[m][1]);
            unpk2(s2[m][1], s[m][2], s[m][3]);
        }

        // ---- mask + online softmax update ----
        if (fast) {
#pragma unroll
            for (int m = 0; m < 4; m++) {
                float mx = -1e30f;
#pragma unroll
                for (int c = 0; c < 4; c++) {
                    float v = s[m][c] * 0.125f;     // 1/sqrt(64)
                    s[m][c] = v;
                    mx = fmaxf(mx, v);
                }
#pragma unroll
                for (int off = 8; off >= 1; off >>= 1)
                    mx = fmaxf(mx, __shfl_xor_sync(0xffffffffu, mx, off));
                const float mnew = fmaxf(m_i[m], mx);
                const float corr = __expf(m_i[m] - mnew);
                m_i[m] = mnew;
                float ps = 0.0f;
#pragma unroll
                for (int c = 0; c < 4; c++) {
                    float p = __expf(s[m][c] - mnew);
                    s[m][c] = p;
                    ps += p;
                }
#pragma unroll
                for (int off = 8; off >= 1; off >>= 1)
                    ps += __shfl_xor_sync(0xffffffffu, ps, off);
                l_i[m] = l_i[m] * corr + ps;
                const unsigned long long c2 = pk_dup(corr);
                mul2(o2[m][0], o2[m][0], c2);
                mul2(o2[m][1], o2[m][1], c2);
            }
        } else {
            const int msk[4] = {mv.x, mv.y, mv.z, mv.w};
#pragma unroll
            for (int m = 0; m < 4; m++) {
                const int r = q0 + ty + 16 * m;    // global query row
                const int jb = j0 + tx * 4;
                float mx = -1e30f;
#pragma unroll
                for (int c = 0; c < 4; c++) {
                    float v = s[m][c] * 0.125f;     // 1/sqrt(64)
                    if ((jb + c > r) || (msk[c] != 0)) v = -1e30f;
                    s[m][c] = v;
                    mx = fmaxf(mx, v);
                }
#pragma unroll
                for (int off = 8; off >= 1; off >>= 1)
                    mx = fmaxf(mx, __shfl_xor_sync(0xffffffffu, mx, off));
                const float mnew = fmaxf(m_i[m], mx);
                const float corr = __expf(m_i[m] - mnew);
                m_i[m] = mnew;
                float ps = 0.0f;
#pragma unroll
                for (int c = 0; c < 4; c++) {
                    float p = __expf(s[m][c] - mnew);
                    s[m][c] = p;
                    ps += p;
                }
#pragma unroll
                for (int off = 8; off >= 1; off >>= 1)
                    ps += __shfl_xor_sync(0xffffffffu, ps, off);
                l_i[m] = l_i[m] * corr + ps;
                const unsigned long long c2 = pk_dup(corr);
                mul2(o2[m][0], o2[m][0], c2);
                mul2(o2[m][1], o2[m][1], c2);
            }
        }

        __syncthreads();  // everyone done reading KPs as K^T
        // ---- write P into KPs (row-major: P[r][j]) ----
#pragma unroll
        for (int m = 0; m < 4; m++) {
            float4 pv;
            pv.x = s[m][0]; pv.y = s[m][1]; pv.z = s[m][2]; pv.w = s[m][3];
            *(float4*)&KPs[(ty + 16 * m) * 64 + tx * 4] = pv;
        }
        __syncthreads();

        // ---- O += P @ V (packed pairs over output columns) ----
        for (int kk = 0; kk < 64; kk += 4) {
            float pa[16];
#pragma unroll
            for (int m = 0; m < 4; m++)
                *(float4*)&pa[m * 4] = *(const float4*)&KPs[(ty + 16 * m) * 64 + kk];
#pragma unroll
            for (int u = 0; u < 4; u++) {
                const unsigned long long* vp =
                    (const unsigned long long*)&Vs[(kk + u) * 64 + tx * 4];
                const unsigned long long v20 = vp[0];
                const unsigned long long v21 = vp[1];
#pragma unroll
                for (int m = 0; m < 4; m++) {
                    const unsigned long long p2 = pk_dup(pa[m * 4 + u]);
                    fma2(o2[m][0], p2, v20);
                    fma2(o2[m][1], p2, v21);
                }
            }
        }
    }

    // ---- normalize + write ----
#pragma unroll
    for (int m = 0; m < 4; m++) {
        const float inv = 1.0f / l_i[m];
        const int r = q0 + ty + 16 * m;
        float o[4];
        unpk2(o2[m][0], o[0], o[1]);
        unpk2(o2[m][1], o[2], o[3]);
        float4 res;
        res.x = o[0] * inv;
        res.y = o[1] * inv;
        res.z = o[2] * inv;
        res.w = o[3] * inv;
        *(float4*)(O + (size_t)(b * SN + r) * DN + h * HDN + tx * 4) = res;
    }
}

// ---------------------------------------------------------------------------
// Launch
// ---------------------------------------------------------------------------
extern "C" void kernel_launch(void* const* d_in, const int* in_sizes, int n_in,
                              void* d_out, int out_size)
{
    const float* X   = (const float*)d_in[0];
    const int*   kpm = (const int*)  d_in[1];
    const float* Wq  = (const float*)d_in[2];
    const float* bq  = (const float*)d_in[3];
    const float* Wk  = (const float*)d_in[4];
    const float* bk  = (const float*)d_in[5];
    const float* Wv  = (const float*)d_in[6];
    const float* bv  = (const float*)d_in[7];
    const float* Wo  = (const float*)d_in[8];
    const float* bo  = (const float*)d_in[9];
    float* out = (float*)d_out;

    float *Qd, *Kd, *Vd, *Ad;
    cudaGetSymbolAddress((void**)&Qd, g_Q);
    cudaGetSymbolAddress((void**)&Kd, g_K);
    cudaGetSymbolAddress((void**)&Vd, g_V);
    cudaGetSymbolAddress((void**)&Ad, g_ATT);

    QKVArgs args;
    args.W[0] = Wq; args.b[0] = bq; args.C[0] = Qd;
    args.W[1] = Wk; args.b[1] = bk; args.C[1] = Kd;
    args.W[2] = Wv; args.b[2] = bv; args.C[2] = Vd;

    dim3 gqkv(DN / 128, NN / 128, 3);   // (8, 32, 3) = 768 CTAs
    dim3 gg(DN / 128, NN / 128);        // (8, 32)
    dim3 bg(256);

    qkv_gemm_kernel<<<gqkv, bg>>>(X, args);

    dim3 ga(SN / 64, BN * HN);          // (32, 32)
    attn_kernel<<<ga, bg>>>(Qd, Kd, Vd, kpm, Ad);

    gemm_bias_kernel<<<gg, bg>>>(Ad, Wo, bo, out);
}

// round 15
// speedup vs baseline: 1.5837x; 1.4737x over previous
#include <cuda_runtime.h>
#include <math.h>
#include <stdint.h>

// Problem constants (fixed by the dataset)
#define BN   2
#define SN   2048
#define DN   1024
#define HN   16
#define HDN  64
#define NN   (BN * SN)   // 4096 tokens

// ---------------------------------------------------------------------------
// Scratch (no cudaMalloc allowed): device globals.
// ---------------------------------------------------------------------------
__device__ float g_Q[NN * DN];
__device__ float g_K[NN * DN];
__device__ float g_V[NN * DN];
__device__ float g_ATT[NN * DN];

// ---------------------------------------------------------------------------
// Helpers
// ---------------------------------------------------------------------------
__device__ __forceinline__ uint32_t f2tf32(float x) {
    uint32_t r;
    asm("cvt.rn.tf32.f32 %0, %1;" : "=r"(r) : "f"(x));
    return r;
}
__device__ __forceinline__ void mma_tf32(float* d, const uint32_t* a, const uint32_t* b) {
    asm volatile(
        "mma.sync.aligned.m16n8k8.row.col.f32.tf32.tf32.f32 "
        "{%0,%1,%2,%3}, {%4,%5,%6,%7}, {%8,%9}, {%0,%1,%2,%3};\n"
        : "+f"(d[0]), "+f"(d[1]), "+f"(d[2]), "+f"(d[3])
        : "r"(a[0]), "r"(a[1]), "r"(a[2]), "r"(a[3]), "r"(b[0]), "r"(b[1]));
}

// Packed f32x2 helpers (used by the attention kernel)
__device__ __forceinline__ unsigned long long pk_dup(float x) {
    unsigned long long r;
    asm("mov.b64 %0, {%1, %1};" : "=l"(r) : "f"(x));
    return r;
}
__device__ __forceinline__ void fma2(unsigned long long& acc,
                                     unsigned long long a,
                                     unsigned long long b) {
    asm("fma.rn.f32x2 %0, %1, %2, %0;" : "+l"(acc) : "l"(a), "l"(b));
}
__device__ __forceinline__ void mul2(unsigned long long& d,
                                     unsigned long long a,
                                     unsigned long long b) {
    asm("mul.rn.f32x2 %0, %1, %2;" : "=l"(d) : "l"(a), "l"(b));
}
__device__ __forceinline__ void unpk2(unsigned long long v, float& lo, float& hi) {
    asm("mov.b64 {%0, %1}, %2;" : "=f"(lo), "=f"(hi) : "l"(v));
}

struct QKVArgs {
    const float* W[3];
    const float* b[3];
    float*       C[3];
};

// ---------------------------------------------------------------------------
// tf32 tensor-core GEMM: C[N x M] = A[N x K] @ W[M x K]^T + bias[M]
// N=4096, M=K=1024. Block 128x128, 8 warps as 4(M)x2(N); warp tile 32x64 =
// 2 m-frags x 8 n-frags of m16n8k8. Smem tiles [128][16] padded to 20 floats
// (fragment reads r*20+q are bank-conflict-free), double-buffered (40 KB).
// fp32 -> tf32 conversion happens ONCE at staging time.
// ---------------------------------------------------------------------------
__device__ __forceinline__
void gemm_tf32_core(const float* __restrict__ A,
                    const float* __restrict__ W,
                    const float* __restrict__ bias,
                    float* __restrict__ C)
{
    const int Kd = DN;

    __shared__ uint32_t As[2][128][20];   // [buf][row][k]  tf32 bits
    __shared__ uint32_t Bs[2][128][20];   // [buf][col][k]  tf32 bits

    const int tid    = threadIdx.x;
    const int lane   = tid & 31;
    const int wid    = tid >> 5;
    const int warp_m = wid & 3;          // 0..3  -> 32-row slice
    const int warp_n = wid >> 2;         // 0..1  -> 64-col slice
    const int gid    = lane >> 2;        // 0..7
    const int qid    = lane & 3;         // 0..3

    const int row0 = blockIdx.y * 128;
    const int col0 = blockIdx.x * 128;

    // staging assignment: thread -> (row, 8-wide k segment)
    const int trow = tid >> 1;           // 0..127
    const int tk   = (tid & 1) * 8;      // 0 or 8

    const float4* Ap = (const float4*)(A + (size_t)(row0 + trow) * Kd + tk);
    const float4* Wp = (const float4*)(W + (size_t)(col0 + trow) * Kd + tk);

    float acc[2][8][4];
#pragma unroll
    for (int fm = 0; fm < 2; fm++)
#pragma unroll
        for (int fn = 0; fn < 8; fn++)
#pragma unroll
            for (int e = 0; e < 4; e++) acc[fm][fn][e] = 0.0f;

    // ---- stage tile 0 ----
    float4 av0 = Ap[0], av1 = Ap[1];
    float4 wv0 = Wp[0], wv1 = Wp[1];
    {
        uint32_t* ad = &As[0][trow][tk];
        ad[0] = f2tf32(av0.x); ad[1] = f2tf32(av0.y);
        ad[2] = f2tf32(av0.z); ad[3] = f2tf32(av0.w);
        ad[4] = f2tf32(av1.x); ad[5] = f2tf32(av1.y);
        ad[6] = f2tf32(av1.z); ad[7] = f2tf32(av1.w);
        uint32_t* bd = &Bs[0][trow][tk];
        bd[0] = f2tf32(wv0.x); bd[1] = f2tf32(wv0.y);
        bd[2] = f2tf32(wv0.z); bd[3] = f2tf32(wv0.w);
        bd[4] = f2tf32(wv1.x); bd[5] = f2tf32(wv1.y);
        bd[6] = f2tf32(wv1.z); bd[7] = f2tf32(wv1.w);
    }
    __syncthreads();

    const int T = Kd / 16;   // 64 K-tiles of depth 16
    for (int t = 0; t < T; t++) {
        const int cur = t & 1;
        const int nxt = cur ^ 1;

        if (t + 1 < T) {
            av0 = Ap[(t + 1) * 4];  av1 = Ap[(t + 1) * 4 + 1];
            wv0 = Wp[(t + 1) * 4];  wv1 = Wp[(t + 1) * 4 + 1];
        }

#pragma unroll
        for (int ks = 0; ks < 16; ks += 8) {
            // A fragments (2 x m16)
            uint32_t afr[2][4];
#pragma unroll
            for (int fm = 0; fm < 2; fm++) {
                const int r = warp_m * 32 + fm * 16 + gid;
                afr[fm][0] = As[cur][r][ks + qid];
                afr[fm][1] = As[cur][r + 8][ks + qid];
                afr[fm][2] = As[cur][r][ks + qid + 4];
                afr[fm][3] = As[cur][r + 8][ks + qid + 4];
            }
            // B fragments (8 x n8)
            uint32_t bfr[8][2];
#pragma unroll
            for (int fn = 0; fn < 8; fn++) {
                const int c = warp_n * 64 + fn * 8 + gid;
                bfr[fn][0] = Bs[cur][c][ks + qid];
                bfr[fn][1] = Bs[cur][c][ks + qid + 4];
            }
#pragma unroll
            for (int fm = 0; fm < 2; fm++)
#pragma unroll
                for (int fn = 0; fn < 8; fn++)
                    mma_tf32(acc[fm][fn], afr[fm], bfr[fn]);
        }

        if (t + 1 < T) {
            uint32_t* ad = &As[nxt][trow][tk];
            ad[0] = f2tf32(av0.x); ad[1] = f2tf32(av0.y);
            ad[2] = f2tf32(av0.z); ad[3] = f2tf32(av0.w);
            ad[4] = f2tf32(av1.x); ad[5] = f2tf32(av1.y);
            ad[6] = f2tf32(av1.z); ad[7] = f2tf32(av1.w);
            uint32_t* bd = &Bs[nxt][trow][tk];
            bd[0] = f2tf32(wv0.x); bd[1] = f2tf32(wv0.y);
            bd[2] = f2tf32(wv0.z); bd[3] = f2tf32(wv0.w);
            bd[4] = f2tf32(wv1.x); bd[5] = f2tf32(wv1.y);
            bd[6] = f2tf32(wv1.z); bd[7] = f2tf32(wv1.w);
            __syncthreads();
        }
    }

    // ---- epilogue: bias + store (D layout: c0=(g,2q) c1=(g,2q+1) c2/c3=+8row)
#pragma unroll
    for (int fm = 0; fm < 2; fm++) {
        const int rg = row0 + warp_m * 32 + fm * 16 + gid;
#pragma unroll
        for (int fn = 0; fn < 8; fn++) {
            const int cg = col0 + warp_n * 64 + fn * 8 + 2 * qid;
            const float b0 = bias[cg];
            const float b1 = bias[cg + 1];
            float2 v0, v1;
            v0.x = acc[fm][fn][0] + b0;  v0.y = acc[fm][fn][1] + b1;
            v1.x = acc[fm][fn][2] + b0;  v1.y = acc[fm][fn][3] + b1;
            *(float2*)(C + (size_t)rg * DN + cg)       = v0;
            *(float2*)(C + (size_t)(rg + 8) * DN + cg) = v1;
        }
    }
}

__global__ __launch_bounds__(256)
void qkv_gemm_kernel(const float* __restrict__ A, QKVArgs args)
{
    const int z = blockIdx.z;
    gemm_tf32_core(A, args.W[z], args.b[z], args.C[z]);
}

__global__ __launch_bounds__(256)
void gemm_bias_kernel(const float* __restrict__ A,
                      const float* __restrict__ W,
                      const float* __restrict__ bias,
                      float* __restrict__ C)
{
    gemm_tf32_core(A, W, bias, C);
}

// ---------------------------------------------------------------------------
// Flash attention (fp32, FFMA2 inner products) — unchanged from the
// 1490.8us passing kernel.
// ---------------------------------------------------------------------------
__global__ __launch_bounds__(256, 2)
void attn_kernel(const float* __restrict__ Qb,
                 const float* __restrict__ Kb,
                 const float* __restrict__ Vb,
                 const int*   __restrict__ kpm,
                 float* __restrict__ O)
{
    __shared__ float Qs[64 * 64];    // Qs[r][k]
    __shared__ float KPs[64 * 64];   // first K^T: KPs[k][j]; then P: KPs[r][j]
    __shared__ float Vs[64 * 64];    // Vs[k][d]

    const int tid = threadIdx.x;
    const int q0  = blockIdx.x * 64;
    const int bh  = blockIdx.y;
    const int b   = bh >> 4;
    const int h   = bh & 15;
    const int tx  = tid & 15;
    const int ty  = tid >> 4;

    // ---- load Q tile ----
    {
        const int r = tid >> 2, seg = tid & 3;
        const float4* src =
            (const float4*)(Qb + (size_t)(b * SN + q0 + r) * DN + h * HDN + seg * 16);
        float4* dst = (float4*)(Qs + r * 64 + seg * 16);
#pragma unroll
        for (int q = 0; q < 4; q++) dst[q] = src[q];
    }

    float m_i[4], l_i[4];
    unsigned long long o2[4][2];
#pragma unroll
    for (int m = 0; m < 4; m++) {
        m_i[m] = -1e30f;
        l_i[m] = 0.0f;
        o2[m][0] = 0ull;
        o2[m][1] = 0ull;
    }

    const int* kpm_b = kpm + b * SN;

    for (int j0 = 0; j0 <= q0; j0 += 64) {
        __syncthreads();

        // ---- load K (transposed into KPs) and V ----
        {
            const int r = tid >> 2, seg = tid & 3;
            const float4* ks =
                (const float4*)(Kb + (size_t)(b * SN + j0 + r) * DN + h * HDN + seg * 16);
#pragma unroll
            for (int q = 0; q < 4; q++) {
                float4 kv = ks[q];
                const int kk = seg * 16 + q * 4;
                KPs[(kk + 0) * 64 + r] = kv.x;
                KPs[(kk + 1) * 64 + r] = kv.y;
                KPs[(kk + 2) * 64 + r] = kv.z;
                KPs[(kk + 3) * 64 + r] = kv.w;
            }
            const float4* vsrc =
                (const float4*)(Vb + (size_t)(b * SN + j0 + r) * DN + h * HDN + seg * 16);
            float4* vdst = (float4*)(Vs + r * 64 + seg * 16);
#pragma unroll
            for (int q = 0; q < 4; q++) vdst[q] = vsrc[q];
        }

        const int4 mv = *(const int4*)(kpm_b + j0 + tx * 4);
        const int tvalid = (mv.x == 0) | (mv.y == 0) | (mv.z == 0) | (mv.w == 0);
        const int tall   = (mv.x == 0) & (mv.y == 0) & (mv.z == 0) & (mv.w == 0);
        const int anyv = __syncthreads_or(tvalid);
        const int allv = __syncthreads_and(tall);
        if (!anyv) continue;
        const bool fast = (j0 + 64 <= q0) && allv;

        // ---- scores (packed pairs) ----
        unsigned long long s2[4][2];
#pragma unroll
        for (int m = 0; m < 4; m++) { s2[m][0] = 0ull; s2[m][1] = 0ull; }

        for (int kk = 0; kk < 64; kk += 4) {
            float qa[16];
#pragma unroll
            for (int m = 0; m < 4; m++)
                *(float4*)&qa[m * 4] = *(const float4*)&Qs[(ty + 16 * m) * 64 + kk];
#pragma unroll
            for (int u = 0; u < 4; u++) {
                const unsigned long long* kp =
                    (const unsigned long long*)&KPs[(kk + u) * 64 + tx * 4];
                const unsigned long long k20 = kp[0];
                const unsigned long long k21 = kp[1];
#pragma unroll
                for (int m = 0; m < 4; m++) {
                    const unsigned long long q2 = pk_dup(qa[m * 4 + u]);
                    fma2(s2[m][0], q2, k20);
                    fma2(s2[m][1], q2, k21);
                }
            }
        }

        float s[4][4];
#pragma unroll
        for (int m = 0; m < 4; m++) {
            unpk2(s2[m][0], s[m][0], s[m][1]);
            unpk2(s2[m][1], s[m][2], s[m][3]);
        }

        // ---- mask + online softmax update ----
        if (fast) {
#pragma unroll
            for (int m = 0; m < 4; m++) {
                float mx = -1e30f;
#pragma unroll
                for (int c = 0; c < 4; c++) {
                    float v = s[m][c] * 0.125f;
                    s[m][c] = v;
                    mx = fmaxf(mx, v);
                }
#pragma unroll
                for (int off = 8; off >= 1; off >>= 1)
                    mx = fmaxf(mx, __shfl_xor_sync(0xffffffffu, mx, off));
                const float mnew = fmaxf(m_i[m], mx);
                const float corr = __expf(m_i[m] - mnew);
                m_i[m] = mnew;
                float ps = 0.0f;
#pragma unroll
                for (int c = 0; c < 4; c++) {
                    float p = __expf(s[m][c] - mnew);
                    s[m][c] = p;
                    ps += p;
                }
#pragma unroll
                for (int off = 8; off >= 1; off >>= 1)
                    ps += __shfl_xor_sync(0xffffffffu, ps, off);
                l_i[m] = l_i[m] * corr + ps;
                const unsigned long long c2 = pk_dup(corr);
                mul2(o2[m][0], o2[m][0], c2);
                mul2(o2[m][1], o2[m][1], c2);
            }
        } else {
            const int msk[4] = {mv.x, mv.y, mv.z, mv.w};
#pragma unroll
            for (int m = 0; m < 4; m++) {
                const int r = q0 + ty + 16 * m;
                const int jb = j0 + tx * 4;
                float mx = -1e30f;
#pragma unroll
                for (int c = 0; c < 4; c++) {
                    float v = s[m][c] * 0.125f;
                    if ((jb + c > r) || (msk[c] != 0)) v = -1e30f;
                    s[m][c] = v;
                    mx = fmaxf(mx, v);
                }
#pragma unroll
                for (int off = 8; off >= 1; off >>= 1)
                    mx = fmaxf(mx, __shfl_xor_sync(0xffffffffu, mx, off));
                const float mnew = fmaxf(m_i[m], mx);
                const float corr = __expf(m_i[m] - mnew);
                m_i[m] = mnew;
                float ps = 0.0f;
#pragma unroll
                for (int c = 0; c < 4; c++) {
                    float p = __expf(s[m][c] - mnew);
                    s[m][c] = p;
                    ps += p;
                }
#pragma unroll
                for (int off = 8; off >= 1; off >>= 1)
                    ps += __shfl_xor_sync(0xffffffffu, ps, off);
                l_i[m] = l_i[m] * corr + ps;
                const unsigned long long c2 = pk_dup(corr);
                mul2(o2[m][0], o2[m][0], c2);
                mul2(o2[m][1], o2[m][1], c2);
            }
        }

        __syncthreads();
#pragma unroll
        for (int m = 0; m < 4; m++) {
            float4 pv;
            pv.x = s[m][0]; pv.y = s[m][1]; pv.z = s[m][2]; pv.w = s[m][3];
            *(float4*)&KPs[(ty + 16 * m) * 64 + tx * 4] = pv;
        }
        __syncthreads();

        // ---- O += P @ V ----
        for (int kk = 0; kk < 64; kk += 4) {
            float pa[16];
#pragma unroll
            for (int m = 0; m < 4; m++)
                *(float4*)&pa[m * 4] = *(const float4*)&KPs[(ty + 16 * m) * 64 + kk];
#pragma unroll
            for (int u = 0; u < 4; u++) {
                const unsigned long long* vp =
                    (const unsigned long long*)&Vs[(kk + u) * 64 + tx * 4];
                const unsigned long long v20 = vp[0];
                const unsigned long long v21 = vp[1];
#pragma unroll
                for (int m = 0; m < 4; m++) {
                    const unsigned long long p2 = pk_dup(pa[m * 4 + u]);
                    fma2(o2[m][0], p2, v20);
                    fma2(o2[m][1], p2, v21);
                }
            }
        }
    }

    // ---- normalize + write ----
#pragma unroll
    for (int m = 0; m < 4; m++) {
        const float inv = 1.0f / l_i[m];
        const int r = q0 + ty + 16 * m;
        float o[4];
        unpk2(o2[m][0], o[0], o[1]);
        unpk2(o2[m][1], o[2], o[3]);
        float4 res;
        res.x = o[0] * inv;
        res.y = o[1] * inv;
        res.z = o[2] * inv;
        res.w = o[3] * inv;
        *(float4*)(O + (size_t)(b * SN + r) * DN + h * HDN + tx * 4) = res;
    }
}

// ---------------------------------------------------------------------------
// Launch
// ---------------------------------------------------------------------------
extern "C" void kernel_launch(void* const* d_in, const int* in_sizes, int n_in,
                              void* d_out, int out_size)
{
    const float* X   = (const float*)d_in[0];
    const int*   kpm = (const int*)  d_in[1];
    const float* Wq  = (const float*)d_in[2];
    const float* bq  = (const float*)d_in[3];
    const float* Wk  = (const float*)d_in[4];
    const float* bk  = (const float*)d_in[5];
    const float* Wv  = (const float*)d_in[6];
    const float* bv  = (const float*)d_in[7];
    const float* Wo  = (const float*)d_in[8];
    const float* bo  = (const float*)d_in[9];
    float* out = (float*)d_out;

    float *Qd, *Kd, *Vd, *Ad;
    cudaGetSymbolAddress((void**)&Qd, g_Q);
    cudaGetSymbolAddress((void**)&Kd, g_K);
    cudaGetSymbolAddress((void**)&Vd, g_V);
    cudaGetSymbolAddress((void**)&Ad, g_ATT);

    QKVArgs args;
    args.W[0] = Wq; args.b[0] = bq; args.C[0] = Qd;
    args.W[1] = Wk; args.b[1] = bk; args.C[1] = Kd;
    args.W[2] = Wv; args.b[2] = bv; args.C[2] = Vd;

    dim3 gqkv(DN / 128, NN / 128, 3);   // (8, 32, 3) = 768 CTAs
    dim3 gg(DN / 128, NN / 128);        // (8, 32)
    dim3 bg(256);

    qkv_gemm_kernel<<<gqkv, bg>>>(X, args);

    dim3 ga(SN / 64, BN * HN);          // (32, 32)
    attn_kernel<<<ga, bg>>>(Qd, Kd, Vd, kpm, Ad);

    gemm_bias_kernel<<<gg, bg>>>(Ad, Wo, bo, out);
}

// round 17
// speedup vs baseline: 2.2006x; 1.3895x over previous
#include <cuda_runtime.h>
#include <math.h>
#include <stdint.h>

// Problem constants (fixed by the dataset)
#define BN   2
#define SN   2048
#define DN   1024
#define HN   16
#define HDN  64
#define NN   (BN * SN)   // 4096 tokens

// ---------------------------------------------------------------------------
// Scratch (no cudaMalloc allowed): device globals.
// ---------------------------------------------------------------------------
__device__ float g_Q[NN * DN];
__device__ float g_K[NN * DN];
__device__ float g_V[NN * DN];
__device__ float g_ATT[NN * DN];

// ---------------------------------------------------------------------------
// Helpers
// ---------------------------------------------------------------------------
__device__ __forceinline__ uint32_t f2tf32(float x) {
    uint32_t r;
    asm("cvt.rn.tf32.f32 %0, %1;" : "=r"(r) : "f"(x));
    return r;
}
__device__ __forceinline__ void mma_tf32(float* d, const uint32_t* a, const uint32_t* b) {
    asm volatile(
        "mma.sync.aligned.m16n8k8.row.col.f32.tf32.tf32.f32 "
        "{%0,%1,%2,%3}, {%4,%5,%6,%7}, {%8,%9}, {%0,%1,%2,%3};\n"
        : "+f"(d[0]), "+f"(d[1]), "+f"(d[2]), "+f"(d[3])
        : "r"(a[0]), "r"(a[1]), "r"(a[2]), "r"(a[3]), "r"(b[0]), "r"(b[1]));
}

struct QKVArgs {
    const float* W[3];
    const float* b[3];
    float*       C[3];
};

// ---------------------------------------------------------------------------
// tf32 tensor-core GEMM (validated R15): C = A @ W^T + bias. Unchanged.
// ---------------------------------------------------------------------------
__device__ __forceinline__
void gemm_tf32_core(const float* __restrict__ A,
                    const float* __restrict__ W,
                    const float* __restrict__ bias,
                    float* __restrict__ C)
{
    const int Kd = DN;

    __shared__ uint32_t As[2][128][20];
    __shared__ uint32_t Bs[2][128][20];

    const int tid    = threadIdx.x;
    const int lane   = tid & 31;
    const int wid    = tid >> 5;
    const int warp_m = wid & 3;
    const int warp_n = wid >> 2;
    const int gid    = lane >> 2;
    const int qid    = lane & 3;

    const int row0 = blockIdx.y * 128;
    const int col0 = blockIdx.x * 128;

    const int trow = tid >> 1;
    const int tk   = (tid & 1) * 8;

    const float4* Ap = (const float4*)(A + (size_t)(row0 + trow) * Kd + tk);
    const float4* Wp = (const float4*)(W + (size_t)(col0 + trow) * Kd + tk);

    float acc[2][8][4];
#pragma unroll
    for (int fm = 0; fm < 2; fm++)
#pragma unroll
        for (int fn = 0; fn < 8; fn++)
#pragma unroll
            for (int e = 0; e < 4; e++) acc[fm][fn][e] = 0.0f;

    float4 av0 = Ap[0], av1 = Ap[1];
    float4 wv0 = Wp[0], wv1 = Wp[1];
    {
        uint32_t* ad = &As[0][trow][tk];
        ad[0] = f2tf32(av0.x); ad[1] = f2tf32(av0.y);
        ad[2] = f2tf32(av0.z); ad[3] = f2tf32(av0.w);
        ad[4] = f2tf32(av1.x); ad[5] = f2tf32(av1.y);
        ad[6] = f2tf32(av1.z); ad[7] = f2tf32(av1.w);
        uint32_t* bd = &Bs[0][trow][tk];
        bd[0] = f2tf32(wv0.x); bd[1] = f2tf32(wv0.y);
        bd[2] = f2tf32(wv0.z); bd[3] = f2tf32(wv0.w);
        bd[4] = f2tf32(wv1.x); bd[5] = f2tf32(wv1.y);
        bd[6] = f2tf32(wv1.z); bd[7] = f2tf32(wv1.w);
    }
    __syncthreads();

    const int T = Kd / 16;
    for (int t = 0; t < T; t++) {
        const int cur = t & 1;
        const int nxt = cur ^ 1;

        if (t + 1 < T) {
            av0 = Ap[(t + 1) * 4];  av1 = Ap[(t + 1) * 4 + 1];
            wv0 = Wp[(t + 1) * 4];  wv1 = Wp[(t + 1) * 4 + 1];
        }

#pragma unroll
        for (int ks = 0; ks < 16; ks += 8) {
            uint32_t afr[2][4];
#pragma unroll
            for (int fm = 0; fm < 2; fm++) {
                const int r = warp_m * 32 + fm * 16 + gid;
                afr[fm][0] = As[cur][r][ks + qid];
                afr[fm][1] = As[cur][r + 8][ks + qid];
                afr[fm][2] = As[cur][r][ks + qid + 4];
                afr[fm][3] = As[cur][r + 8][ks + qid + 4];
            }
            uint32_t bfr[8][2];
#pragma unroll
            for (int fn = 0; fn < 8; fn++) {
                const int c = warp_n * 64 + fn * 8 + gid;
                bfr[fn][0] = Bs[cur][c][ks + qid];
                bfr[fn][1] = Bs[cur][c][ks + qid + 4];
            }
#pragma unroll
            for (int fm = 0; fm < 2; fm++)
#pragma unroll
                for (int fn = 0; fn < 8; fn++)
                    mma_tf32(acc[fm][fn], afr[fm], bfr[fn]);
        }

        if (t + 1 < T) {
            uint32_t* ad = &As[nxt][trow][tk];
            ad[0] = f2tf32(av0.x); ad[1] = f2tf32(av0.y);
            ad[2] = f2tf32(av0.z); ad[3] = f2tf32(av0.w);
            ad[4] = f2tf32(av1.x); ad[5] = f2tf32(av1.y);
            ad[6] = f2tf32(av1.z); ad[7] = f2tf32(av1.w);
            uint32_t* bd = &Bs[nxt][trow][tk];
            bd[0] = f2tf32(wv0.x); bd[1] = f2tf32(wv0.y);
            bd[2] = f2tf32(wv0.z); bd[3] = f2tf32(wv0.w);
            bd[4] = f2tf32(wv1.x); bd[5] = f2tf32(wv1.y);
            bd[6] = f2tf32(wv1.z); bd[7] = f2tf32(wv1.w);
            __syncthreads();
        }
    }

#pragma unroll
    for (int fm = 0; fm < 2; fm++) {
        const int rg = row0 + warp_m * 32 + fm * 16 + gid;
#pragma unroll
        for (int fn = 0; fn < 8; fn++) {
            const int cg = col0 + warp_n * 64 + fn * 8 + 2 * qid;
            const float b0 = bias[cg];
            const float b1 = bias[cg + 1];
            float2 v0, v1;
            v0.x = acc[fm][fn][0] + b0;  v0.y = acc[fm][fn][1] + b1;
            v1.x = acc[fm][fn][2] + b0;  v1.y = acc[fm][fn][3] + b1;
            *(float2*)(C + (size_t)rg * DN + cg)       = v0;
            *(float2*)(C + (size_t)(rg + 8) * DN + cg) = v1;
        }
    }
}

__global__ __launch_bounds__(256)
void qkv_gemm_kernel(const float* __restrict__ A, QKVArgs args)
{
    const int z = blockIdx.z;
    gemm_tf32_core(A, args.W[z], args.b[z], args.C[z]);
}

__global__ __launch_bounds__(256)
void gemm_bias_kernel(const float* __restrict__ A,
                      const float* __restrict__ W,
                      const float* __restrict__ bias,
                      float* __restrict__ C)
{
    gemm_tf32_core(A, W, bias, C);
}

// ---------------------------------------------------------------------------
// Flash attention, tf32 MMA for QK^T and P@V.
// 128 threads = 4 warps; warp w owns query rows w*16..w*16+15 and ALL 64
// keys (8 n-frags) -> every softmax row is complete within one quad, so
// row reductions are shfl_xor(1,2) only. No cross-warp reduction.
// Smem: KPs = K [key][hd] then P [q][key]; Vt = Q staging then V^T [d][key].
// ld=68 words -> fragment LDS covers all 32 banks, conflict-free.
// ---------------------------------------------------------------------------
#define LDA 68

__global__ __launch_bounds__(128)
void attn_mma_kernel(const float* __restrict__ Qb,
                     const float* __restrict__ Kb,
                     const float* __restrict__ Vb,
                     const int*   __restrict__ kpm,
                     float* __restrict__ O)
{
    __shared__ uint32_t KPs[64 * LDA];   // K [key][hd] -> P [q][key]
    __shared__ uint32_t Vt[64 * LDA];    // Q staging [q][hd] -> V^T [d][key]

    const int tid  = threadIdx.x;
    const int lane = tid & 31;
    const int wid  = tid >> 5;           // 0..3: 16-row query slice
    const int gid  = lane >> 2;
    const int qid  = lane & 3;

    const int q0 = blockIdx.x * 64;
    const int bh = blockIdx.y;
    const int b  = bh >> 4;
    const int h  = bh & 15;

    const int r    = tid >> 1;           // staging row 0..63
    const int half = (tid & 1) * 32;     // 32-float half of the row

    // ---- stage Q (tf32) into Vt, then hoist fragments ----
    {
        const float4* src =
            (const float4*)(Qb + (size_t)(b * SN + q0 + r) * DN + h * HDN + half);
        uint32_t* dst = &Vt[r * LDA + half];
#pragma unroll
        for (int v4 = 0; v4 < 8; v4++) {
            float4 x = src[v4];
            dst[v4 * 4 + 0] = f2tf32(x.x);
            dst[v4 * 4 + 1] = f2tf32(x.y);
            dst[v4 * 4 + 2] = f2tf32(x.z);
            dst[v4 * 4 + 3] = f2tf32(x.w);
        }
    }
    __syncthreads();

    uint32_t qf[8][4];                   // Q fragments: 8 k-steps over HD=64
    {
        const int qr = wid * 16 + gid;
#pragma unroll
        for (int ks = 0; ks < 8; ks++) {
            qf[ks][0] = Vt[qr * LDA + ks * 8 + qid];
            qf[ks][1] = Vt[(qr + 8) * LDA + ks * 8 + qid];
            qf[ks][2] = Vt[qr * LDA + ks * 8 + qid + 4];
            qf[ks][3] = Vt[(qr + 8) * LDA + ks * 8 + qid + 4];
        }
    }

    float m_i[2] = {-1e30f, -1e30f};
    float l_i[2] = {0.0f, 0.0f};
    float oacc[8][4];                    // O fragments: 8 n-frags over HD=64
#pragma unroll
    for (int fn = 0; fn < 8; fn++)
#pragma unroll
        for (int e = 0; e < 4; e++) oacc[fn][e] = 0.0f;

    const int* kpm_b = kpm + b * SN;
    const int r0 = q0 + wid * 16 + gid;  // global query row (half 0)
    const int r1 = r0 + 8;               // global query row (half 1)

    for (int j0 = 0; j0 <= q0; j0 += 64) {
        __syncthreads();   // prev iter's smem reads (and Q hoist) complete

        // ---- stage K [key][hd] and V^T [d][key] (tf32) ----
        {
            const float4* ksrc =
                (const float4*)(Kb + (size_t)(b * SN + j0 + r) * DN + h * HDN + half);
            uint32_t* kdst = &KPs[r * LDA + half];
#pragma unroll
            for (int v4 = 0; v4 < 8; v4++) {
                float4 x = ksrc[v4];
                kdst[v4 * 4 + 0] = f2tf32(x.x);
                kdst[v4 * 4 + 1] = f2tf32(x.y);
                kdst[v4 * 4 + 2] = f2tf32(x.z);
                kdst[v4 * 4 + 3] = f2tf32(x.w);
            }
            const float4* vsrc =
                (const float4*)(Vb + (size_t)(b * SN + j0 + r) * DN + h * HDN + half);
#pragma unroll
            for (int v4 = 0; v4 < 8; v4++) {
                float4 x = vsrc[v4];
                const int d0 = half + v4 * 4;
                Vt[(d0 + 0) * LDA + r] = f2tf32(x.x);
                Vt[(d0 + 1) * LDA + r] = f2tf32(x.y);
                Vt[(d0 + 2) * LDA + r] = f2tf32(x.z);
                Vt[(d0 + 3) * LDA + r] = f2tf32(x.w);
            }
        }

        // key-padding ballots (barriers also order the staging writes)
        const int4 mv = *(const int4*)(kpm_b + j0 + (tid & 15) * 4);
        const int tvalid = (mv.x == 0) | (mv.y == 0) | (mv.z == 0) | (mv.w == 0);
        const int tall   = (mv.x == 0) & (mv.y == 0) & (mv.z == 0) & (mv.w == 0);
        const int anyv = __syncthreads_or(tvalid);
        const int allv = __syncthreads_and(tall);
        if (!anyv) continue;
        const bool fast = (j0 + 64 <= q0) && allv;

        // ---- S = Q @ K^T (tf32 MMA): 16 rows x 64 keys per warp ----
        float sf[8][4];
#pragma unroll
        for (int fn = 0; fn < 8; fn++)
#pragma unroll
            for (int e = 0; e < 4; e++) sf[fn][e] = 0.0f;

#pragma unroll
        for (int ks = 0; ks < 8; ks++) {
#pragma unroll
            for (int fn = 0; fn < 8; fn++) {
                const int n0 = fn * 8 + gid;        // key index in tile
                uint32_t bfr[2];
                bfr[0] = KPs[n0 * LDA + ks * 8 + qid];
                bfr[1] = KPs[n0 * LDA + ks * 8 + qid + 4];
                mma_tf32(sf[fn], qf[ks], bfr);
            }
        }

        // ---- masking (diagonal/padded tiles only) ----
        if (!fast) {
#pragma unroll
            for (int fn = 0; fn < 8; fn++) {
                const int c = j0 + fn * 8 + 2 * qid;
                const int p0 = kpm_b[c];
                const int p1 = kpm_b[c + 1];
                if ((c > r0)     || p0) sf[fn][0] = -1e30f;
                if ((c + 1 > r0) || p1) sf[fn][1] = -1e30f;
                if ((c > r1)     || p0) sf[fn][2] = -1e30f;
                if ((c + 1 > r1) || p1) sf[fn][3] = -1e30f;
            }
        }

        // ---- online softmax (rows complete within each quad) ----
        float mx0 = -1e30f, mx1 = -1e30f;
#pragma unroll
        for (int fn = 0; fn < 8; fn++) {
#pragma unroll
            for (int e = 0; e < 4; e++) sf[fn][e] *= 0.125f;   // 1/sqrt(64)
            mx0 = fmaxf(mx0, fmaxf(sf[fn][0], sf[fn][1]));
            mx1 = fmaxf(mx1, fmaxf(sf[fn][2], sf[fn][3]));
        }
#pragma unroll
        for (int off = 1; off <= 2; off <<= 1) {
            mx0 = fmaxf(mx0, __shfl_xor_sync(0xffffffffu, mx0, off));
            mx1 = fmaxf(mx1, __shfl_xor_sync(0xffffffffu, mx1, off));
        }
        const float mn0 = fmaxf(m_i[0], mx0);
        const float mn1 = fmaxf(m_i[1], mx1);
        const float cr0 = __expf(m_i[0] - mn0);
        const float cr1 = __expf(m_i[1] - mn1);
        m_i[0] = mn0;  m_i[1] = mn1;

        float ps0 = 0.0f, ps1 = 0.0f;
#pragma unroll
        for (int fn = 0; fn < 8; fn++) {
            sf[fn][0] = __expf(sf[fn][0] - mn0);
            sf[fn][1] = __expf(sf[fn][1] - mn0);
            sf[fn][2] = __expf(sf[fn][2] - mn1);
            sf[fn][3] = __expf(sf[fn][3] - mn1);
            ps0 += sf[fn][0] + sf[fn][1];
            ps1 += sf[fn][2] + sf[fn][3];
        }
#pragma unroll
        for (int off = 1; off <= 2; off <<= 1) {
            ps0 += __shfl_xor_sync(0xffffffffu, ps0, off);
            ps1 += __shfl_xor_sync(0xffffffffu, ps1, off);
        }
        l_i[0] = l_i[0] * cr0 + ps0;
        l_i[1] = l_i[1] * cr1 + ps1;
#pragma unroll
        for (int fn = 0; fn < 8; fn++) {
            oacc[fn][0] *= cr0;  oacc[fn][1] *= cr0;
            oacc[fn][2] *= cr1;  oacc[fn][3] *= cr1;
        }

        __syncthreads();   // all warps done reading KPs as K

        // ---- write P (tf32) into KPs as [q][key] ----
        {
            const int pr = wid * 16 + gid;
#pragma unroll
            for (int fn = 0; fn < 8; fn++) {
                const int pc = fn * 8 + 2 * qid;
                uint2 a, bb2;
                a.x   = f2tf32(sf[fn][0]);  a.y   = f2tf32(sf[fn][1]);
                bb2.x = f2tf32(sf[fn][2]);  bb2.y = f2tf32(sf[fn][3]);
                *(uint2*)&KPs[pr * LDA + pc]       = a;
                *(uint2*)&KPs[(pr + 8) * LDA + pc] = bb2;
            }
        }
        __syncthreads();

        // ---- O += P @ V (tf32 MMA); A = P [q][key], B = Vt [d][key] ----
        {
            const int pr = wid * 16 + gid;
#pragma unroll
            for (int ks = 0; ks < 8; ks++) {
                uint32_t afr[4];
                afr[0] = KPs[pr * LDA + ks * 8 + qid];
                afr[1] = KPs[(pr + 8) * LDA + ks * 8 + qid];
                afr[2] = KPs[pr * LDA + ks * 8 + qid + 4];
                afr[3] = KPs[(pr + 8) * LDA + ks * 8 + qid + 4];
#pragma unroll
                for (int fn = 0; fn < 8; fn++) {
                    const int n0 = fn * 8 + gid;    // head dim
                    uint32_t bfr[2];
                    bfr[0] = Vt[n0 * LDA + ks * 8 + qid];
                    bfr[1] = Vt[n0 * LDA + ks * 8 + qid + 4];
                    mma_tf32(oacc[fn], afr, bfr);
                }
            }
        }
    }

    // ---- normalize + write O ----
    const float inv0 = 1.0f / l_i[0];
    const float inv1 = 1.0f / l_i[1];
#pragma unroll
    for (int fn = 0; fn < 8; fn++) {
        const int cg = fn * 8 + 2 * qid;
        float2 v0, v1;
        v0.x = oacc[fn][0] * inv0;  v0.y = oacc[fn][1] * inv0;
        v1.x = oacc[fn][2] * inv1;  v1.y = oacc[fn][3] * inv1;
        *(float2*)(O + (size_t)(b * SN + r0) * DN + h * HDN + cg) = v0;
        *(float2*)(O + (size_t)(b * SN + r1) * DN + h * HDN + cg) = v1;
    }
}

// ---------------------------------------------------------------------------
// Launch
// ---------------------------------------------------------------------------
extern "C" void kernel_launch(void* const* d_in, const int* in_sizes, int n_in,
                              void* d_out, int out_size)
{
    const float* X   = (const float*)d_in[0];
    const int*   kpm = (const int*)  d_in[1];
    const float* Wq  = (const float*)d_in[2];
    const float* bq  = (const float*)d_in[3];
    const float* Wk  = (const float*)d_in[4];
    const float* bk  = (const float*)d_in[5];
    const float* Wv  = (const float*)d_in[6];
    const float* bv  = (const float*)d_in[7];
    const float* Wo  = (const float*)d_in[8];
    const float* bo  = (const float*)d_in[9];
    float* out = (float*)d_out;

    float *Qd, *Kd, *Vd, *Ad;
    cudaGetSymbolAddress((void**)&Qd, g_Q);
    cudaGetSymbolAddress((void**)&Kd, g_K);
    cudaGetSymbolAddress((void**)&Vd, g_V);
    cudaGetSymbolAddress((void**)&Ad, g_ATT);

    QKVArgs args;
    args.W[0] = Wq; args.b[0] = bq; args.C[0] = Qd;
    args.W[1] = Wk; args.b[1] = bk; args.C[1] = Kd;
    args.W[2] = Wv; args.b[2] = bv; args.C[2] = Vd;

    dim3 gqkv(DN / 128, NN / 128, 3);   // (8, 32, 3)
    dim3 gg(DN / 128, NN / 128);        // (8, 32)
    dim3 bg(256);

    qkv_gemm_kernel<<<gqkv, bg>>>(X, args);

    dim3 ga(SN / 64, BN * HN);          // (32, 32)
    attn_mma_kernel<<<ga, 128>>>(Qd, Kd, Vd, kpm, Ad);

    gemm_bias_kernel<<<gg, bg>>>(Ad, Wo, bo, out);
}